// round 11
// baseline (speedup 1.0000x reference)
#include <cuda_runtime.h>
#include <cuda_bf16.h>
#include <cuda_fp8.h>
#include <cstdint>

#define R_TOT 8192     // B*S
#define D_DIM 1024
#define V_DIM 16384
#define NGRP  64       // col groups (grid.y), 256 cols each
#define NCAND 128      // candidate slots per row: 64 groups x 2 warp-halves
#define F8SCALE 16.0f  // q,k scaled by 16 before e4m3; sims scaled by 256

// ---------------- device scratch ----------------
__device__ float g_inv_x[R_TOT];
__device__ float g_inv_d[V_DIM];
__device__ uint8_t g_qf8[(size_t)R_TOT * D_DIM];   // normalized x * 16, e4m3
__device__ uint8_t g_kf8[(size_t)V_DIM * D_DIM];   // normalized dict * 16, e4m3
__device__ float g_cv[R_TOT][NCAND][2];
__device__ int   g_ci[R_TOT][NCAND][2];
__device__ __nv_bfloat16 g_ehi[(size_t)R_TOT * D_DIM];   // e_ln hi
__device__ __nv_bfloat16 g_elo[(size_t)R_TOT * D_DIM];   // e_ln lo
__device__ __nv_bfloat16 g_whiT[(size_t)D_DIM * D_DIM];  // o_w^T hi
__device__ __nv_bfloat16 g_wloT[(size_t)D_DIM * D_DIM];  // o_w^T lo

__device__ __forceinline__ uint32_t smem_u32(const void* p) {
    uint32_t a;
    asm("{ .reg .u64 t; cvta.to.shared.u64 t, %1; cvt.u32.u64 %0, t; }" : "=r"(a) : "l"(p));
    return a;
}

// ---------------- block reduce (256 threads) ----------------
__device__ __forceinline__ float block_sum_256(float v, float* red) {
    #pragma unroll
    for (int o = 16; o; o >>= 1) v += __shfl_down_sync(0xffffffffu, v, o);
    int lane = threadIdx.x & 31, wid = threadIdx.x >> 5;
    __syncthreads();
    if (lane == 0) red[wid] = v;
    __syncthreads();
    float t = (threadIdx.x < 8) ? red[threadIdx.x] : 0.f;
    if (wid == 0) {
        #pragma unroll
        for (int o = 4; o; o >>= 1) t += __shfl_down_sync(0xffffffffu, t, o);
        if (lane == 0) red[0] = t;
    }
    __syncthreads();
    return red[0];
}

__device__ __forceinline__ float block_max_256(float v, float* red) {
    #pragma unroll
    for (int o = 16; o; o >>= 1) v = fmaxf(v, __shfl_xor_sync(0xffffffffu, v, o));
    int lane = threadIdx.x & 31, wid = threadIdx.x >> 5;
    __syncthreads();
    if (lane == 0) red[wid] = v;
    __syncthreads();
    float t = (threadIdx.x < 8) ? red[threadIdx.x] : -1e30f;
    if (wid == 0) {
        #pragma unroll
        for (int o = 4; o; o >>= 1) t = fmaxf(t, __shfl_xor_sync(0xffffffffu, t, o));
        if (lane == 0) red[0] = t;
    }
    __syncthreads();
    return red[0];
}

// ---------------- L2-normalize + fp8 convert ----------------
__global__ void norm_convert_kernel(const float* __restrict__ src, int which) {
    int row = blockIdx.x;
    const float* p = src + (size_t)row * D_DIM;
    int tid = threadIdx.x;
    float4 v = *(const float4*)(p + tid * 4);
    float s = v.x * v.x + v.y * v.y + v.z * v.z + v.w * v.w;
    __shared__ float red[32];
    float ss = block_sum_256(s, red);
    float inv = rsqrtf(fmaxf(ss, 1e-12f)) * F8SCALE;
    uint8_t* dst = (which == 0 ? g_qf8 : g_kf8) + (size_t)row * D_DIM + tid * 4;
    __nv_fp8x2_storage_t p0 = __nv_cvt_float2_to_fp8x2(make_float2(v.x * inv, v.y * inv),
                                                       __NV_SATFINITE, __NV_E4M3);
    __nv_fp8x2_storage_t p1 = __nv_cvt_float2_to_fp8x2(make_float2(v.z * inv, v.w * inv),
                                                       __NV_SATFINITE, __NV_E4M3);
    *(uint32_t*)dst = (uint32_t)p0 | ((uint32_t)p1 << 16);
    if (tid == 0) {
        float invn = inv * (1.0f / F8SCALE);
        if (which == 0) g_inv_x[row] = invn; else g_inv_d[row] = invn;
    }
}

// ---------------- common MMA machinery ----------------
#define STAGE_B 32768           // A 16KB + B 16KB (128 rows x 128 bytes each)
#define NSTAGE 3
#define MMA_SMEM (NSTAGE * STAGE_B)

#define CPA16(dst, src) \
    asm volatile("cp.async.cg.shared.global [%0], [%1], 16;" :: "r"(dst), "l"(src))
#define CPA_COMMIT() asm volatile("cp.async.commit_group;" ::: "memory")
#define CPA_WAIT1()  asm volatile("cp.async.wait_group 1;" ::: "memory")

#define LDMX4(r0, r1, r2, r3, addr) \
    asm volatile("ldmatrix.sync.aligned.m8n8.x4.shared.b16 {%0,%1,%2,%3}, [%4];" \
        : "=r"(r0), "=r"(r1), "=r"(r2), "=r"(r3) : "r"(addr))

#define MMA16816(d, a, b0, b1) \
    asm volatile("mma.sync.aligned.m16n8k16.row.col.f32.bf16.bf16.f32 " \
        "{%0,%1,%2,%3}, {%4,%5,%6,%7}, {%8,%9}, {%0,%1,%2,%3};" \
        : "+f"((d)[0]), "+f"((d)[1]), "+f"((d)[2]), "+f"((d)[3]) \
        : "r"((a)[0]), "r"((a)[1]), "r"((a)[2]), "r"((a)[3]), "r"(b0), "r"(b1))

#define MMAF8(d, a, b0, b1) \
    asm volatile("mma.sync.aligned.m16n8k32.row.col.f32.e4m3.e4m3.f32 " \
        "{%0,%1,%2,%3}, {%4,%5,%6,%7}, {%8,%9}, {%0,%1,%2,%3};" \
        : "+f"((d)[0]), "+f"((d)[1]), "+f"((d)[2]), "+f"((d)[3]) \
        : "r"((a)[0]), "r"((a)[1]), "r"((a)[2]), "r"((a)[3]), "r"(b0), "r"(b1))

#define INSERT(q, v, ix) do { \
    if ((v) > tv1[q] || ((v) == tv1[q] && (ix) < ti1[q])) { \
        tv2[q] = tv1[q]; ti2[q] = ti1[q]; tv1[q] = (v); ti1[q] = (ix); \
    } else if ((v) > tv2[q] || ((v) == tv2[q] && (ix) < ti2[q])) { \
        tv2[q] = (v); ti2[q] = (ix); \
    } } while (0)

#define LOADER_SETUP() \
    int lrow[4], lkg[4]; uint32_t ldst[4]; \
    _Pragma("unroll") \
    for (int i = 0; i < 4; i++) { \
        int u = tid + i * 256; \
        lrow[i] = u >> 3; lkg[i] = u & 7; \
        ldst[i] = (uint32_t)(lrow[i] * 128 + ((lkg[i] ^ (lrow[i] & 7)) << 4)); \
    }

#define LDM_SETUP() \
    int a_row[2], b_row[4]; int a_kgb, b_kgb; \
    { \
        a_kgb = lane >> 4; \
        a_row[0] = wm + (lane & 15); \
        a_row[1] = wm + 16 + (lane & 15); \
        int bg = lane >> 3; \
        b_kgb = bg & 1; \
        _Pragma("unroll") \
        for (int p = 0; p < 4; p++) \
            b_row[p] = wn + (p * 2 + (bg >> 1)) * 8 + (lane & 7); \
    }

// one 128-byte-row chunk of MMAs (bf16: K=64; fp8: K=128); addressing identical
#define COMPUTE_CHUNK_GEN(aS, bS, MMAOP) \
    _Pragma("unroll") \
    for (int ks = 0; ks < 4; ks++) { \
        uint32_t a[2][4]; \
        _Pragma("unroll") \
        for (int mt = 0; mt < 2; mt++) { \
            int kg = ks * 2 + a_kgb; \
            uint32_t addr = (aS) + a_row[mt] * 128 + ((kg ^ (a_row[mt] & 7)) << 4); \
            LDMX4(a[mt][0], a[mt][1], a[mt][2], a[mt][3], addr); \
        } \
        _Pragma("unroll") \
        for (int p = 0; p < 4; p++) { \
            uint32_t b[4]; \
            int kg = ks * 2 + b_kgb; \
            uint32_t addr = (bS) + b_row[p] * 128 + ((kg ^ (b_row[p] & 7)) << 4); \
            LDMX4(b[0], b[1], b[2], b[3], addr); \
            _Pragma("unroll") \
            for (int mt = 0; mt < 2; mt++) { \
                MMAOP(acc[mt][p * 2 + 0], a[mt], b[0], b[1]); \
                MMAOP(acc[mt][p * 2 + 1], a[mt], b[2], b[3]); \
            } \
        } \
    }

// ---------------- fp8 mma sim-GEMM + per-row top-2 ----------------
// grid (64 m-tiles, 64 col-groups). Each CTA: 128 rows x 256 cols (2 n-tiles),
// K=1024 in 128-elt (128B) chunks: 16 flat chunks, 3-stage cp.async ring.
__global__ void __launch_bounds__(256, 2)
simmma_kernel() {
    extern __shared__ char sm[];
    uint32_t sb = smem_u32(sm);
    const int tid = threadIdx.x, lane = tid & 31, w = tid >> 5;
    const int wm = (w & 3) * 32, wn = (w >> 2) * 64;
    const int rb = blockIdx.x * 128;
    const int cb = blockIdx.y * 256;

    LOADER_SETUP();
    LDM_SETUP();

    float tv1[4], tv2[4]; int ti1[4], ti2[4];
    #pragma unroll
    for (int q = 0; q < 4; q++) { tv1[q] = -1e30f; tv2[q] = -1e30f; ti1[q] = 0; ti2[q] = 0; }

    const uint8_t* Ab = g_qf8 + (size_t)rb * D_DIM;
    const uint8_t* Bb = g_kf8 + (size_t)cb * D_DIM;

    // prologue: chunks 0,1 -> stages 0,1  (chunk h: nt = h>>3, kc = h&7)
    #pragma unroll
    for (int h = 0; h < 2; h++) {
        uint32_t stg = sb + h * STAGE_B;
        #pragma unroll
        for (int i = 0; i < 4; i++) {
            CPA16(stg + ldst[i],         Ab + (size_t)lrow[i] * D_DIM + h * 128 + lkg[i] * 16);
            CPA16(stg + 16384 + ldst[i], Bb + (size_t)lrow[i] * D_DIM + h * 128 + lkg[i] * 16);
        }
        CPA_COMMIT();
    }
    CPA_WAIT1();
    __syncthreads();

    float acc[2][8][4];
    int st = 0;
    #pragma unroll 1
    for (int g = 0; g < 16; g++) {
        int kc = g & 7, nt = g >> 3;
        if (kc == 0) {
            #pragma unroll
            for (int mt = 0; mt < 2; mt++)
                #pragma unroll
                for (int j = 0; j < 8; j++)
                    #pragma unroll
                    for (int c = 0; c < 4; c++) acc[mt][j][c] = 0.f;
        }
        uint32_t aS = sb + st * STAGE_B;
        uint32_t bS = aS + 16384;
        COMPUTE_CHUNK_GEN(aS, bS, MMAF8);
        if (kc == 7) {
            int colbase = cb + nt * 128 + wn + (lane & 3) * 2;
            #pragma unroll
            for (int mt = 0; mt < 2; mt++)
                #pragma unroll
                for (int h2 = 0; h2 < 2; h2++) {
                    int q = mt * 2 + h2;
                    #pragma unroll
                    for (int j = 0; j < 8; j++) {
                        float v0 = acc[mt][j][h2 * 2 + 0];
                        float v1 = acc[mt][j][h2 * 2 + 1];
                        int c0 = colbase + j * 8;
                        INSERT(q, v0, c0);
                        INSERT(q, v1, c0 + 1);
                    }
                }
        }
        // issue chunk g+2 into stage (st+2)%3
        int h = g + 2;
        if (h < 16) {
            int kch = h & 7, nth = h >> 3;
            int sti = st + 2; if (sti >= 3) sti -= 3;
            uint32_t stg = sb + sti * STAGE_B;
            const uint8_t* Ac = Ab + kch * 128;
            const uint8_t* Bc = Bb + (size_t)(nth * 128) * D_DIM + kch * 128;
            #pragma unroll
            for (int i = 0; i < 4; i++) {
                CPA16(stg + ldst[i],         Ac + (size_t)lrow[i] * D_DIM + lkg[i] * 16);
                CPA16(stg + 16384 + ldst[i], Bc + (size_t)lrow[i] * D_DIM + lkg[i] * 16);
            }
        }
        CPA_COMMIT();
        CPA_WAIT1();
        __syncthreads();
        st++; if (st >= 3) st = 0;
    }

    // merge top-2 across the 4 lanes of each quad
    #pragma unroll
    for (int off = 1; off <= 2; off <<= 1) {
        #pragma unroll
        for (int q = 0; q < 4; q++) {
            float ov1 = __shfl_xor_sync(0xffffffffu, tv1[q], off);
            int   oi1 = __shfl_xor_sync(0xffffffffu, ti1[q], off);
            float ov2 = __shfl_xor_sync(0xffffffffu, tv2[q], off);
            int   oi2 = __shfl_xor_sync(0xffffffffu, ti2[q], off);
            INSERT(q, ov1, oi1);
            INSERT(q, ov2, oi2);
        }
    }
    if ((lane & 3) == 0) {
        int slot = blockIdx.y * 2 + (w >> 2);
        #pragma unroll
        for (int q = 0; q < 4; q++) {
            int row = rb + wm + (q >> 1) * 16 + (q & 1) * 8 + (lane >> 2);
            g_cv[row][slot][0] = tv1[q]; g_ci[row][slot][0] = ti1[q];
            g_cv[row][slot][1] = tv2[q]; g_ci[row][slot][1] = ti2[q];
        }
    }
}

// ---------------- fused: exact fp32 rescore + STE + LayerNorm ----------------
// candidate values are scaled by F8SCALE^2 = 256; margin 2.0 ~= 7.8e-3 sim units.
__global__ void rescore_ln_kernel(const float* __restrict__ X, const float* __restrict__ Dw,
                                  const float* __restrict__ gamma, const float* __restrict__ beta,
                                  float* __restrict__ out, int write_aux) {
    int row = blockIdx.x;
    int tid = threadIdx.x;
    __shared__ float red[32];
    __shared__ int cl[32];
    __shared__ int s_cnt;
    __shared__ float s_best; __shared__ int s_bidx;
    float mv = g_cv[row][tid >> 1][tid & 1];
    int   mi = g_ci[row][tid >> 1][tid & 1];
    float vmax = block_max_256(mv, red);
    if (tid == 0) { s_cnt = 0; s_best = -9.f; s_bidx = 0x7FFFFFFF; }
    __syncthreads();
    if (mv >= vmax - 2.0f) {
        int pos = atomicAdd(&s_cnt, 1);
        if (pos < 32) cl[pos] = mi;
    }
    __syncthreads();
    int cnt = s_cnt; if (cnt > 32) cnt = 32;
    float inva = g_inv_x[row];
    const float4* xr = (const float4*)(X + (size_t)row * D_DIM);
    float4 xv = xr[tid];
    for (int c = 0; c < cnt; c++) {
        int idx = cl[c];
        const float4* dr = (const float4*)(Dw + (size_t)idx * D_DIM);
        float4 dv = dr[tid];
        float part = xv.x * dv.x + xv.y * dv.y + xv.z * dv.z + xv.w * dv.w;
        float tot = block_sum_256(part, red);
        if (tid == 0) {
            float sim = tot * inva * g_inv_d[idx];
            if (sim > s_best || (sim == s_best && idx < s_bidx)) { s_best = sim; s_bidx = idx; }
        }
        __syncthreads();
    }
    if (tid == 0 && write_aux) { out[row] = (float)s_bidx; out[R_TOT + row] = s_best; }
    __syncthreads();
    int idx = s_bidx;

    // ---- STE + LayerNorm ----
    const float* xrf = X + (size_t)row * D_DIM;
    const float* zr = Dw + (size_t)idx * D_DIM;
    float ev[4];
    float s = 0.f;
    #pragma unroll
    for (int t = 0; t < 4; t++) {
        int j = t * 256 + tid;
        float xvv = xrf[j], zv = zr[j];
        ev[t] = (zv - xvv) + xvv;
        s += ev[t];
    }
    float mu = block_sum_256(s, red) * (1.0f / D_DIM);
    float ss = 0.f;
    #pragma unroll
    for (int t = 0; t < 4; t++) { float d = ev[t] - mu; ss += d * d; }
    float var = block_sum_256(ss, red) * (1.0f / D_DIM);
    float rsig = rsqrtf(var + 1e-6f);
    #pragma unroll
    for (int t = 0; t < 4; t++) {
        int j = t * 256 + tid;
        float v = (ev[t] - mu) * rsig * gamma[j] + beta[j];
        __nv_bfloat16 hi = __float2bfloat16(v);
        float lo = v - __bfloat162float(hi);
        size_t off = (size_t)row * D_DIM + j;
        g_ehi[off] = hi;
        g_elo[off] = __float2bfloat16(lo);
    }
}

// ---------------- o_w transpose + hi/lo split ----------------
__global__ void splitw_kernel(const float* __restrict__ W) {
    __shared__ float tile[32][33];
    int bk = blockIdx.x * 32, bn = blockIdx.y * 32;
    int tx = threadIdx.x, ty = threadIdx.y;  // 32 x 8
    #pragma unroll
    for (int r = 0; r < 32; r += 8)
        tile[ty + r][tx] = W[(size_t)(bk + ty + r) * D_DIM + bn + tx];
    __syncthreads();
    #pragma unroll
    for (int r = 0; r < 32; r += 8) {
        float v = tile[tx][ty + r];
        __nv_bfloat16 hi = __float2bfloat16(v);
        float lo = v - __bfloat162float(hi);
        size_t off = (size_t)(bn + ty + r) * D_DIM + bk + tx;
        g_whiT[off] = hi;
        g_wloT[off] = __float2bfloat16(lo);
    }
}

// ---------------- output projection: 3-term bf16 split GEMM ----------------
__global__ void __launch_bounds__(256, 2)
outmma_kernel(float* __restrict__ Out) {
    extern __shared__ char sm[];
    uint32_t sb = smem_u32(sm);
    const int tid = threadIdx.x, lane = tid & 31, w = tid >> 5;
    const int wm = (w & 3) * 32, wn = (w >> 2) * 64;
    const int rb = blockIdx.x * 128;
    const int cbN = blockIdx.y * 128;

    LOADER_SETUP();
    LDM_SETUP();

    const int NCH = 48;

    auto a_src = [&](int h) -> const __nv_bfloat16* {
        int seg = h >> 4, kc = h & 15;
        const __nv_bfloat16* base = (seg < 2) ? g_ehi : g_elo;
        return base + (size_t)rb * D_DIM + kc * 64;
    };
    auto b_src = [&](int h) -> const __nv_bfloat16* {
        int seg = h >> 4, kc = h & 15;
        const __nv_bfloat16* base = (seg == 1) ? g_wloT : g_whiT;
        return base + (size_t)cbN * D_DIM + kc * 64;
    };

    #pragma unroll
    for (int h = 0; h < 2; h++) {
        uint32_t stg = sb + h * STAGE_B;
        const __nv_bfloat16* Ac = a_src(h);
        const __nv_bfloat16* Bc = b_src(h);
        #pragma unroll
        for (int i = 0; i < 4; i++) {
            CPA16(stg + ldst[i],         Ac + (size_t)lrow[i] * D_DIM + lkg[i] * 8);
            CPA16(stg + 16384 + ldst[i], Bc + (size_t)lrow[i] * D_DIM + lkg[i] * 8);
        }
        CPA_COMMIT();
    }
    CPA_WAIT1();
    __syncthreads();

    float acc[2][8][4];
    #pragma unroll
    for (int mt = 0; mt < 2; mt++)
        #pragma unroll
        for (int j = 0; j < 8; j++)
            #pragma unroll
            for (int c = 0; c < 4; c++) acc[mt][j][c] = 0.f;

    int st = 0;
    #pragma unroll 1
    for (int g = 0; g < NCH; g++) {
        uint32_t aS = sb + st * STAGE_B;
        uint32_t bS = aS + 16384;
        COMPUTE_CHUNK_GEN(aS, bS, MMA16816);
        int h = g + 2;
        if (h < NCH) {
            int sti = st + 2; if (sti >= 3) sti -= 3;
            uint32_t stg = sb + sti * STAGE_B;
            const __nv_bfloat16* Ac = a_src(h);
            const __nv_bfloat16* Bc = b_src(h);
            #pragma unroll
            for (int i = 0; i < 4; i++) {
                CPA16(stg + ldst[i],         Ac + (size_t)lrow[i] * D_DIM + lkg[i] * 8);
                CPA16(stg + 16384 + ldst[i], Bc + (size_t)lrow[i] * D_DIM + lkg[i] * 8);
            }
        }
        CPA_COMMIT();
        CPA_WAIT1();
        __syncthreads();
        st++; if (st >= 3) st = 0;
    }

    #pragma unroll
    for (int mt = 0; mt < 2; mt++) {
        int row0 = rb + wm + mt * 16 + (lane >> 2);
        #pragma unroll
        for (int j = 0; j < 8; j++) {
            int col = cbN + wn + j * 8 + (lane & 3) * 2;
            *(float2*)(Out + (size_t)row0 * D_DIM + col) = make_float2(acc[mt][j][0], acc[mt][j][1]);
            *(float2*)(Out + (size_t)(row0 + 8) * D_DIM + col) = make_float2(acc[mt][j][2], acc[mt][j][3]);
        }
    }
}

extern "C" void kernel_launch(void* const* d_in, const int* in_sizes, int n_in,
                              void* d_out, int out_size) {
    const float* x     = (const float*)d_in[0];
    const float* dw    = (const float*)d_in[1];
    const float* gamma = (const float*)d_in[2];
    const float* beta  = (const float*)d_in[3];
    const float* ow    = (const float*)d_in[4];
    float* out = (float*)d_out;

    const int out_elems = R_TOT * D_DIM;
    int write_aux = (out_size >= out_elems + 2 * R_TOT) ? 1 : 0;
    size_t out_off = write_aux ? (size_t)(2 * R_TOT) : 0;

    cudaFuncSetAttribute(simmma_kernel, cudaFuncAttributeMaxDynamicSharedMemorySize, MMA_SMEM);
    cudaFuncSetAttribute(outmma_kernel, cudaFuncAttributeMaxDynamicSharedMemorySize, MMA_SMEM);

    norm_convert_kernel<<<R_TOT, 256>>>(x, 0);
    norm_convert_kernel<<<V_DIM, 256>>>(dw, 1);
    splitw_kernel<<<dim3(D_DIM / 32, D_DIM / 32), dim3(32, 8)>>>(ow);
    simmma_kernel<<<dim3(R_TOT / 128, NGRP), 256, MMA_SMEM>>>();
    rescore_ln_kernel<<<R_TOT, 256>>>(x, dw, gamma, beta, out, write_aux);
    outmma_kernel<<<dim3(R_TOT / 128, D_DIM / 128), 256, MMA_SMEM>>>(out + out_off);
}

// round 12
// speedup vs baseline: 1.0687x; 1.0687x over previous
#include <cuda_runtime.h>
#include <cuda_bf16.h>
#include <cstdint>

#define R_TOT 8192     // B*S
#define D_DIM 1024
#define V_DIM 16384
#define NCAND 256      // candidate slots per row: 128 col-groups x 2 n-warps

// ---------------- device scratch ----------------
__device__ float g_inv_x[R_TOT];
__device__ float g_inv_d[V_DIM];
__device__ __nv_bfloat16 g_qbf[(size_t)R_TOT * D_DIM];   // normalized x, bf16
__device__ __nv_bfloat16 g_kbf[(size_t)V_DIM * D_DIM];   // normalized dict, bf16
__device__ float g_cv[R_TOT][NCAND][2];
__device__ int   g_ci[R_TOT][NCAND][2];
__device__ __nv_bfloat16 g_ehi[(size_t)R_TOT * D_DIM];   // e_ln hi
__device__ __nv_bfloat16 g_elo[(size_t)R_TOT * D_DIM];   // e_ln lo
__device__ __nv_bfloat16 g_whiT[(size_t)D_DIM * D_DIM];  // o_w^T hi
__device__ __nv_bfloat16 g_wloT[(size_t)D_DIM * D_DIM];  // o_w^T lo

__device__ __forceinline__ uint32_t smem_u32(const void* p) {
    uint32_t a;
    asm("{ .reg .u64 t; cvta.to.shared.u64 t, %1; cvt.u32.u64 %0, t; }" : "=r"(a) : "l"(p));
    return a;
}

// ---------------- block reduce (256 threads) ----------------
__device__ __forceinline__ float block_sum_256(float v, float* red) {
    #pragma unroll
    for (int o = 16; o; o >>= 1) v += __shfl_down_sync(0xffffffffu, v, o);
    int lane = threadIdx.x & 31, wid = threadIdx.x >> 5;
    __syncthreads();
    if (lane == 0) red[wid] = v;
    __syncthreads();
    float t = (threadIdx.x < 8) ? red[threadIdx.x] : 0.f;
    if (wid == 0) {
        #pragma unroll
        for (int o = 4; o; o >>= 1) t += __shfl_down_sync(0xffffffffu, t, o);
        if (lane == 0) red[0] = t;
    }
    __syncthreads();
    return red[0];
}

__device__ __forceinline__ float block_max_256(float v, float* red) {
    #pragma unroll
    for (int o = 16; o; o >>= 1) v = fmaxf(v, __shfl_xor_sync(0xffffffffu, v, o));
    int lane = threadIdx.x & 31, wid = threadIdx.x >> 5;
    __syncthreads();
    if (lane == 0) red[wid] = v;
    __syncthreads();
    float t = (threadIdx.x < 8) ? red[threadIdx.x] : -1e30f;
    if (wid == 0) {
        #pragma unroll
        for (int o = 4; o; o >>= 1) t = fmaxf(t, __shfl_xor_sync(0xffffffffu, t, o));
        if (lane == 0) red[0] = t;
    }
    __syncthreads();
    return red[0];
}

// ---------------- L2-normalize + bf16 convert ----------------
__global__ void norm_convert_kernel(const float* __restrict__ src, int which) {
    int row = blockIdx.x;
    const float* p = src + (size_t)row * D_DIM;
    int tid = threadIdx.x;
    float4 v = *(const float4*)(p + tid * 4);
    float s = v.x * v.x + v.y * v.y + v.z * v.z + v.w * v.w;
    __shared__ float red[32];
    float ss = block_sum_256(s, red);
    float inv = rsqrtf(fmaxf(ss, 1e-12f));
    __nv_bfloat16* dst = (which == 0 ? g_qbf : g_kbf) + (size_t)row * D_DIM + tid * 4;
    __nv_bfloat162 a = __floats2bfloat162_rn(v.x * inv, v.y * inv);
    __nv_bfloat162 b = __floats2bfloat162_rn(v.z * inv, v.w * inv);
    *(__nv_bfloat162*)(dst)     = a;
    *(__nv_bfloat162*)(dst + 2) = b;
    if (tid == 0) { if (which == 0) g_inv_x[row] = inv; else g_inv_d[row] = inv; }
}

// ---------------- common MMA machinery ----------------
#define STAGE_B 32768           // A 16KB + B 16KB (128 rows x 128 bytes each)
#define NSTAGE 3
#define MMA_SMEM (NSTAGE * STAGE_B)

#define CPA16(dst, src) \
    asm volatile("cp.async.cg.shared.global [%0], [%1], 16;" :: "r"(dst), "l"(src))
#define CPA_COMMIT() asm volatile("cp.async.commit_group;" ::: "memory")
#define CPA_WAIT1()  asm volatile("cp.async.wait_group 1;" ::: "memory")

#define LDMX4(r0, r1, r2, r3, addr) \
    asm volatile("ldmatrix.sync.aligned.m8n8.x4.shared.b16 {%0,%1,%2,%3}, [%4];" \
        : "=r"(r0), "=r"(r1), "=r"(r2), "=r"(r3) : "r"(addr))

#define MMA16816(d, a, b0, b1) \
    asm volatile("mma.sync.aligned.m16n8k16.row.col.f32.bf16.bf16.f32 " \
        "{%0,%1,%2,%3}, {%4,%5,%6,%7}, {%8,%9}, {%0,%1,%2,%3};" \
        : "+f"((d)[0]), "+f"((d)[1]), "+f"((d)[2]), "+f"((d)[3]) \
        : "r"((a)[0]), "r"((a)[1]), "r"((a)[2]), "r"((a)[3]), "r"(b0), "r"(b1))

#define INSERT(q, v, ix) do { \
    if ((v) > tv1[q] || ((v) == tv1[q] && (ix) < ti1[q])) { \
        tv2[q] = tv1[q]; ti2[q] = ti1[q]; tv1[q] = (v); ti1[q] = (ix); \
    } else if ((v) > tv2[q] || ((v) == tv2[q] && (ix) < ti2[q])) { \
        tv2[q] = (v); ti2[q] = (ix); \
    } } while (0)

// 256-thread loader mapping (outmma)
#define LOADER_SETUP_256() \
    int lrow[4], lkg[4]; uint32_t ldst[4]; \
    _Pragma("unroll") \
    for (int i = 0; i < 4; i++) { \
        int u = tid + i * 256; \
        lrow[i] = u >> 3; lkg[i] = u & 7; \
        ldst[i] = (uint32_t)(lrow[i] * 128 + ((lkg[i] ^ (lrow[i] & 7)) << 4)); \
    }

#define LDM_SETUP_32x64() \
    int a_row[2], b_row[4]; int a_kgb, b_kgb; \
    { \
        a_kgb = lane >> 4; \
        a_row[0] = wm + (lane & 15); \
        a_row[1] = wm + 16 + (lane & 15); \
        int bg = lane >> 3; \
        b_kgb = bg & 1; \
        _Pragma("unroll") \
        for (int p = 0; p < 4; p++) \
            b_row[p] = wn + (p * 2 + (bg >> 1)) * 8 + (lane & 7); \
    }

#define COMPUTE_CHUNK_32x64(aS, bS) \
    _Pragma("unroll") \
    for (int ks = 0; ks < 4; ks++) { \
        uint32_t a[2][4]; \
        _Pragma("unroll") \
        for (int mt = 0; mt < 2; mt++) { \
            int kg = ks * 2 + a_kgb; \
            uint32_t addr = (aS) + a_row[mt] * 128 + ((kg ^ (a_row[mt] & 7)) << 4); \
            LDMX4(a[mt][0], a[mt][1], a[mt][2], a[mt][3], addr); \
        } \
        _Pragma("unroll") \
        for (int p = 0; p < 4; p++) { \
            uint32_t b[4]; \
            int kg = ks * 2 + b_kgb; \
            uint32_t addr = (bS) + b_row[p] * 128 + ((kg ^ (b_row[p] & 7)) << 4); \
            LDMX4(b[0], b[1], b[2], b[3], addr); \
            _Pragma("unroll") \
            for (int mt = 0; mt < 2; mt++) { \
                MMA16816(acc[mt][p * 2 + 0], a[mt], b[0], b[1]); \
                MMA16816(acc[mt][p * 2 + 1], a[mt], b[2], b[3]); \
            } \
        } \
    }

// ---------------- bf16 sim-GEMM, 128-thread CTA, 64x64 warp tiles ----------------
// grid (64 m-tiles, 128 col-tiles). CTA 128x128, 4 warps (2m x 2n), warp 64x64.
// 16 K-chunks (k64 each), 3-stage cp.async ring.
__global__ void __launch_bounds__(128, 2)
simmma_kernel() {
    extern __shared__ char sm[];
    uint32_t sb = smem_u32(sm);
    const int tid = threadIdx.x, lane = tid & 31, w = tid >> 5;
    const int wm = (w >> 1) * 64, wn = (w & 1) * 64;
    const int rb = blockIdx.x * 128;
    const int cb = blockIdx.y * 128;

    // loader: 8 x 16B per operand per chunk (128 threads)
    int lrow[8], lkg[8]; uint32_t ldst[8];
    #pragma unroll
    for (int i = 0; i < 8; i++) {
        int u = tid + i * 128;
        lrow[i] = u >> 3; lkg[i] = u & 7;
        ldst[i] = (uint32_t)(lrow[i] * 128 + ((lkg[i] ^ (lrow[i] & 7)) << 4));
    }

    // ldmatrix offsets: A 4 m16 tiles, B 4 n16 groups (64 cols)
    int a_row[4], b_row[4]; int a_kgb, b_kgb;
    {
        a_kgb = lane >> 4;
        #pragma unroll
        for (int mt = 0; mt < 4; mt++) a_row[mt] = wm + mt * 16 + (lane & 15);
        int bg = lane >> 3;
        b_kgb = bg & 1;
        #pragma unroll
        for (int p = 0; p < 4; p++)
            b_row[p] = wn + (p * 2 + (bg >> 1)) * 8 + (lane & 7);
    }

    const __nv_bfloat16* Ab = g_qbf + (size_t)rb * D_DIM;
    const __nv_bfloat16* Bb = g_kbf + (size_t)cb * D_DIM;

    // prologue: chunks 0,1 -> stages 0,1
    #pragma unroll
    for (int h = 0; h < 2; h++) {
        uint32_t stg = sb + h * STAGE_B;
        #pragma unroll
        for (int i = 0; i < 8; i++) {
            CPA16(stg + ldst[i],         Ab + (size_t)lrow[i] * D_DIM + h * 64 + lkg[i] * 8);
            CPA16(stg + 16384 + ldst[i], Bb + (size_t)lrow[i] * D_DIM + h * 64 + lkg[i] * 8);
        }
        CPA_COMMIT();
    }
    CPA_WAIT1();
    __syncthreads();

    float acc[4][8][4];
    #pragma unroll
    for (int mt = 0; mt < 4; mt++)
        #pragma unroll
        for (int j = 0; j < 8; j++)
            #pragma unroll
            for (int c = 0; c < 4; c++) acc[mt][j][c] = 0.f;

    int st = 0;
    #pragma unroll 1
    for (int g = 0; g < 16; g++) {
        uint32_t aS = sb + st * STAGE_B;
        uint32_t bS = aS + 16384;
        // compute chunk g
        #pragma unroll
        for (int ks = 0; ks < 4; ks++) {
            uint32_t a[4][4];
            #pragma unroll
            for (int mt = 0; mt < 4; mt++) {
                int kg = ks * 2 + a_kgb;
                uint32_t addr = aS + a_row[mt] * 128 + ((kg ^ (a_row[mt] & 7)) << 4);
                LDMX4(a[mt][0], a[mt][1], a[mt][2], a[mt][3], addr);
            }
            #pragma unroll
            for (int p = 0; p < 4; p++) {
                uint32_t b[4];
                int kg = ks * 2 + b_kgb;
                uint32_t addr = bS + b_row[p] * 128 + ((kg ^ (b_row[p] & 7)) << 4);
                LDMX4(b[0], b[1], b[2], b[3], addr);
                #pragma unroll
                for (int mt = 0; mt < 4; mt++) {
                    MMA16816(acc[mt][p * 2 + 0], a[mt], b[0], b[1]);
                    MMA16816(acc[mt][p * 2 + 1], a[mt], b[2], b[3]);
                }
            }
        }
        // issue chunk g+2
        int h = g + 2;
        if (h < 16) {
            int sti = st + 2; if (sti >= 3) sti -= 3;
            uint32_t stg = sb + sti * STAGE_B;
            const __nv_bfloat16* Ac = Ab + h * 64;
            const __nv_bfloat16* Bc = Bb + h * 64;
            #pragma unroll
            for (int i = 0; i < 8; i++) {
                CPA16(stg + ldst[i],         Ac + (size_t)lrow[i] * D_DIM + lkg[i] * 8);
                CPA16(stg + 16384 + ldst[i], Bc + (size_t)lrow[i] * D_DIM + lkg[i] * 8);
            }
        }
        CPA_COMMIT();
        CPA_WAIT1();
        __syncthreads();
        st++; if (st >= 3) st = 0;
    }

    // per-row top-2 over this warp's 64 cols
    float tv1[8], tv2[8]; int ti1[8], ti2[8];
    #pragma unroll
    for (int q = 0; q < 8; q++) { tv1[q] = -2.f; tv2[q] = -2.f; ti1[q] = 0; ti2[q] = 0; }
    int colbase = cb + wn + (lane & 3) * 2;
    #pragma unroll
    for (int mt = 0; mt < 4; mt++)
        #pragma unroll
        for (int h2 = 0; h2 < 2; h2++) {
            int q = mt * 2 + h2;
            #pragma unroll
            for (int j = 0; j < 8; j++) {
                float v0 = acc[mt][j][h2 * 2 + 0];
                float v1 = acc[mt][j][h2 * 2 + 1];
                int c0 = colbase + j * 8;
                INSERT(q, v0, c0);
                INSERT(q, v1, c0 + 1);
            }
        }
    // merge across the 4 lanes of each quad
    #pragma unroll
    for (int off = 1; off <= 2; off <<= 1) {
        #pragma unroll
        for (int q = 0; q < 8; q++) {
            float ov1 = __shfl_xor_sync(0xffffffffu, tv1[q], off);
            int   oi1 = __shfl_xor_sync(0xffffffffu, ti1[q], off);
            float ov2 = __shfl_xor_sync(0xffffffffu, tv2[q], off);
            int   oi2 = __shfl_xor_sync(0xffffffffu, ti2[q], off);
            INSERT(q, ov1, oi1);
            INSERT(q, ov2, oi2);
        }
    }
    if ((lane & 3) == 0) {
        int slot = blockIdx.y * 2 + (w & 1);
        #pragma unroll
        for (int q = 0; q < 8; q++) {
            int row = rb + wm + (q >> 1) * 16 + (q & 1) * 8 + (lane >> 2);
            g_cv[row][slot][0] = tv1[q]; g_ci[row][slot][0] = ti1[q];
            g_cv[row][slot][1] = tv2[q]; g_ci[row][slot][1] = ti2[q];
        }
    }
}

// ---------------- fused: exact fp32 rescore + STE + LayerNorm ----------------
__global__ void rescore_ln_kernel(const float* __restrict__ X, const float* __restrict__ Dw,
                                  const float* __restrict__ gamma, const float* __restrict__ beta,
                                  float* __restrict__ out, int write_aux) {
    int row = blockIdx.x;
    int tid = threadIdx.x;
    __shared__ float red[32];
    __shared__ int cl[32];
    __shared__ int s_cnt;
    __shared__ float s_best; __shared__ int s_bidx;
    float e0 = g_cv[row][tid][0]; int i0 = g_ci[row][tid][0];
    float e1 = g_cv[row][tid][1]; int i1 = g_ci[row][tid][1];
    float vmax = block_max_256(fmaxf(e0, e1), red);
    if (tid == 0) { s_cnt = 0; s_best = -9.f; s_bidx = 0x7FFFFFFF; }
    __syncthreads();
    if (e0 >= vmax - 1e-3f) { int pos = atomicAdd(&s_cnt, 1); if (pos < 32) cl[pos] = i0; }
    if (e1 >= vmax - 1e-3f) { int pos = atomicAdd(&s_cnt, 1); if (pos < 32) cl[pos] = i1; }
    __syncthreads();
    int cnt = s_cnt; if (cnt > 32) cnt = 32;
    float inva = g_inv_x[row];
    const float4* xr = (const float4*)(X + (size_t)row * D_DIM);
    float4 xv = xr[tid];
    for (int c = 0; c < cnt; c++) {
        int idx = cl[c];
        const float4* dr = (const float4*)(Dw + (size_t)idx * D_DIM);
        float4 dv = dr[tid];
        float part = xv.x * dv.x + xv.y * dv.y + xv.z * dv.z + xv.w * dv.w;
        float tot = block_sum_256(part, red);
        if (tid == 0) {
            float sim = tot * inva * g_inv_d[idx];
            if (sim > s_best || (sim == s_best && idx < s_bidx)) { s_best = sim; s_bidx = idx; }
        }
        __syncthreads();
    }
    if (tid == 0 && write_aux) { out[row] = (float)s_bidx; out[R_TOT + row] = s_best; }
    __syncthreads();
    int idx = s_bidx;

    // ---- STE + LayerNorm ----
    const float* xrf = X + (size_t)row * D_DIM;
    const float* zr = Dw + (size_t)idx * D_DIM;
    float ev[4];
    float s = 0.f;
    #pragma unroll
    for (int t = 0; t < 4; t++) {
        int j = t * 256 + tid;
        float xvv = xrf[j], zv = zr[j];
        ev[t] = (zv - xvv) + xvv;
        s += ev[t];
    }
    float mu = block_sum_256(s, red) * (1.0f / D_DIM);
    float ss = 0.f;
    #pragma unroll
    for (int t = 0; t < 4; t++) { float d = ev[t] - mu; ss += d * d; }
    float var = block_sum_256(ss, red) * (1.0f / D_DIM);
    float rsig = rsqrtf(var + 1e-6f);
    #pragma unroll
    for (int t = 0; t < 4; t++) {
        int j = t * 256 + tid;
        float v = (ev[t] - mu) * rsig * gamma[j] + beta[j];
        __nv_bfloat16 hi = __float2bfloat16(v);
        float lo = v - __bfloat162float(hi);
        size_t off = (size_t)row * D_DIM + j;
        g_ehi[off] = hi;
        g_elo[off] = __float2bfloat16(lo);
    }
}

// ---------------- o_w transpose + hi/lo split ----------------
__global__ void splitw_kernel(const float* __restrict__ W) {
    __shared__ float tile[32][33];
    int bk = blockIdx.x * 32, bn = blockIdx.y * 32;
    int tx = threadIdx.x, ty = threadIdx.y;  // 32 x 8
    #pragma unroll
    for (int r = 0; r < 32; r += 8)
        tile[ty + r][tx] = W[(size_t)(bk + ty + r) * D_DIM + bn + tx];
    __syncthreads();
    #pragma unroll
    for (int r = 0; r < 32; r += 8) {
        float v = tile[tx][ty + r];
        __nv_bfloat16 hi = __float2bfloat16(v);
        float lo = v - __bfloat162float(hi);
        size_t off = (size_t)(bn + ty + r) * D_DIM + bk + tx;
        g_whiT[off] = hi;
        g_wloT[off] = __float2bfloat16(lo);
    }
}

// ---------------- output projection: 3-term bf16 split GEMM (256 thr) ----------------
__global__ void __launch_bounds__(256, 2)
outmma_kernel(float* __restrict__ Out) {
    extern __shared__ char sm[];
    uint32_t sb = smem_u32(sm);
    const int tid = threadIdx.x, lane = tid & 31, w = tid >> 5;
    const int wm = (w & 3) * 32, wn = (w >> 2) * 64;
    const int rb = blockIdx.x * 128;
    const int cbN = blockIdx.y * 128;

    LOADER_SETUP_256();
    LDM_SETUP_32x64();

    const int NCH = 48;

    auto a_src = [&](int h) -> const __nv_bfloat16* {
        int seg = h >> 4, kc = h & 15;
        const __nv_bfloat16* base = (seg < 2) ? g_ehi : g_elo;
        return base + (size_t)rb * D_DIM + kc * 64;
    };
    auto b_src = [&](int h) -> const __nv_bfloat16* {
        int seg = h >> 4, kc = h & 15;
        const __nv_bfloat16* base = (seg == 1) ? g_wloT : g_whiT;
        return base + (size_t)cbN * D_DIM + kc * 64;
    };

    #pragma unroll
    for (int h = 0; h < 2; h++) {
        uint32_t stg = sb + h * STAGE_B;
        const __nv_bfloat16* Ac = a_src(h);
        const __nv_bfloat16* Bc = b_src(h);
        #pragma unroll
        for (int i = 0; i < 4; i++) {
            CPA16(stg + ldst[i],         Ac + (size_t)lrow[i] * D_DIM + lkg[i] * 8);
            CPA16(stg + 16384 + ldst[i], Bc + (size_t)lrow[i] * D_DIM + lkg[i] * 8);
        }
        CPA_COMMIT();
    }
    CPA_WAIT1();
    __syncthreads();

    float acc[2][8][4];
    #pragma unroll
    for (int mt = 0; mt < 2; mt++)
        #pragma unroll
        for (int j = 0; j < 8; j++)
            #pragma unroll
            for (int c = 0; c < 4; c++) acc[mt][j][c] = 0.f;

    int st = 0;
    #pragma unroll 1
    for (int g = 0; g < NCH; g++) {
        uint32_t aS = sb + st * STAGE_B;
        uint32_t bS = aS + 16384;
        COMPUTE_CHUNK_32x64(aS, bS);
        int h = g + 2;
        if (h < NCH) {
            int sti = st + 2; if (sti >= 3) sti -= 3;
            uint32_t stg = sb + sti * STAGE_B;
            const __nv_bfloat16* Ac = a_src(h);
            const __nv_bfloat16* Bc = b_src(h);
            #pragma unroll
            for (int i = 0; i < 4; i++) {
                CPA16(stg + ldst[i],         Ac + (size_t)lrow[i] * D_DIM + lkg[i] * 8);
                CPA16(stg + 16384 + ldst[i], Bc + (size_t)lrow[i] * D_DIM + lkg[i] * 8);
            }
        }
        CPA_COMMIT();
        CPA_WAIT1();
        __syncthreads();
        st++; if (st >= 3) st = 0;
    }

    #pragma unroll
    for (int mt = 0; mt < 2; mt++) {
        int row0 = rb + wm + mt * 16 + (lane >> 2);
        #pragma unroll
        for (int j = 0; j < 8; j++) {
            int col = cbN + wn + j * 8 + (lane & 3) * 2;
            *(float2*)(Out + (size_t)row0 * D_DIM + col) = make_float2(acc[mt][j][0], acc[mt][j][1]);
            *(float2*)(Out + (size_t)(row0 + 8) * D_DIM + col) = make_float2(acc[mt][j][2], acc[mt][j][3]);
        }
    }
}

extern "C" void kernel_launch(void* const* d_in, const int* in_sizes, int n_in,
                              void* d_out, int out_size) {
    const float* x     = (const float*)d_in[0];
    const float* dw    = (const float*)d_in[1];
    const float* gamma = (const float*)d_in[2];
    const float* beta  = (const float*)d_in[3];
    const float* ow    = (const float*)d_in[4];
    float* out = (float*)d_out;

    const int out_elems = R_TOT * D_DIM;
    int write_aux = (out_size >= out_elems + 2 * R_TOT) ? 1 : 0;
    size_t out_off = write_aux ? (size_t)(2 * R_TOT) : 0;

    cudaFuncSetAttribute(simmma_kernel, cudaFuncAttributeMaxDynamicSharedMemorySize, MMA_SMEM);
    cudaFuncSetAttribute(outmma_kernel, cudaFuncAttributeMaxDynamicSharedMemorySize, MMA_SMEM);

    norm_convert_kernel<<<R_TOT, 256>>>(x, 0);
    norm_convert_kernel<<<V_DIM, 256>>>(dw, 1);
    splitw_kernel<<<dim3(D_DIM / 32, D_DIM / 32), dim3(32, 8)>>>(ow);
    simmma_kernel<<<dim3(R_TOT / 128, V_DIM / 128), 128, MMA_SMEM>>>();
    rescore_ln_kernel<<<R_TOT, 256>>>(x, dw, gamma, beta, out, write_aux);
    outmma_kernel<<<dim3(R_TOT / 128, D_DIM / 128), 256, MMA_SMEM>>>(out + out_off);
}

// round 15
// speedup vs baseline: 1.1648x; 1.0899x over previous
#include <cuda_runtime.h>
#include <cuda_bf16.h>
#include <cstdint>

#define R_TOT 8192     // B*S
#define D_DIM 1024
#define V_DIM 16384
#define NGRP  64       // col groups (grid.y), 256 cols each
#define NCAND 128      // candidate slots per row: 64 groups x 2 warp-halves

// ---------------- device scratch ----------------
__device__ float g_inv_x[R_TOT];
__device__ float g_inv_d[V_DIM];
__device__ __nv_bfloat16 g_qbf[(size_t)R_TOT * D_DIM];   // normalized x, bf16
__device__ __nv_bfloat16 g_kbf[(size_t)V_DIM * D_DIM];   // normalized dict, bf16
__device__ float g_cv[R_TOT][NCAND][2];
__device__ int   g_ci[R_TOT][NCAND][2];
__device__ __nv_bfloat16 g_ehi[(size_t)R_TOT * D_DIM];   // e_ln hi
__device__ __nv_bfloat16 g_elo[(size_t)R_TOT * D_DIM];   // e_ln lo
__device__ __nv_bfloat16 g_whiT[(size_t)D_DIM * D_DIM];  // o_w^T hi
__device__ __nv_bfloat16 g_wloT[(size_t)D_DIM * D_DIM];  // o_w^T lo

__device__ __forceinline__ uint32_t smem_u32(const void* p) {
    uint32_t a;
    asm("{ .reg .u64 t; cvta.to.shared.u64 t, %1; cvt.u32.u64 %0, t; }" : "=r"(a) : "l"(p));
    return a;
}

// ---------------- block reduce (256 threads) ----------------
__device__ __forceinline__ float block_sum_256(float v, float* red) {
    #pragma unroll
    for (int o = 16; o; o >>= 1) v += __shfl_down_sync(0xffffffffu, v, o);
    int lane = threadIdx.x & 31, wid = threadIdx.x >> 5;
    __syncthreads();
    if (lane == 0) red[wid] = v;
    __syncthreads();
    float t = (threadIdx.x < 8) ? red[threadIdx.x] : 0.f;
    if (wid == 0) {
        #pragma unroll
        for (int o = 4; o; o >>= 1) t += __shfl_down_sync(0xffffffffu, t, o);
        if (lane == 0) red[0] = t;
    }
    __syncthreads();
    return red[0];
}

__device__ __forceinline__ float block_max_256(float v, float* red) {
    #pragma unroll
    for (int o = 16; o; o >>= 1) v = fmaxf(v, __shfl_xor_sync(0xffffffffu, v, o));
    int lane = threadIdx.x & 31, wid = threadIdx.x >> 5;
    __syncthreads();
    if (lane == 0) red[wid] = v;
    __syncthreads();
    float t = (threadIdx.x < 8) ? red[threadIdx.x] : -1e30f;
    if (wid == 0) {
        #pragma unroll
        for (int o = 4; o; o >>= 1) t = fmaxf(t, __shfl_xor_sync(0xffffffffu, t, o));
        if (lane == 0) red[0] = t;
    }
    __syncthreads();
    return red[0];
}

// ---------------- fused preprocessing ----------------
// blocks [0, R_TOT)                : normalize+bf16 x rows
// blocks [R_TOT, R_TOT+V_DIM)      : normalize+bf16 dict rows
// blocks [R_TOT+V_DIM, +1024)      : o_w transpose + hi/lo split (32x32 tiles)
__global__ void preproc_kernel(const float* __restrict__ x, const float* __restrict__ dw,
                               const float* __restrict__ W) {
    int b = blockIdx.x;
    int tid = threadIdx.x;
    if (b < R_TOT + V_DIM) {
        int which = (b < R_TOT) ? 0 : 1;
        int row = which ? (b - R_TOT) : b;
        const float* p = (which ? dw : x) + (size_t)row * D_DIM;
        float4 v = *(const float4*)(p + tid * 4);
        float s = v.x * v.x + v.y * v.y + v.z * v.z + v.w * v.w;
        __shared__ float red[32];
        float ss = block_sum_256(s, red);
        float inv = rsqrtf(fmaxf(ss, 1e-12f));
        __nv_bfloat16* dst = (which == 0 ? g_qbf : g_kbf) + (size_t)row * D_DIM + tid * 4;
        __nv_bfloat162 a = __floats2bfloat162_rn(v.x * inv, v.y * inv);
        __nv_bfloat162 bb = __floats2bfloat162_rn(v.z * inv, v.w * inv);
        *(__nv_bfloat162*)(dst)     = a;
        *(__nv_bfloat162*)(dst + 2) = bb;
        if (tid == 0) { if (which == 0) g_inv_x[row] = inv; else g_inv_d[row] = inv; }
    } else {
        int t = b - (R_TOT + V_DIM);            // 0..1023
        int bk = (t & 31) * 32, bn = (t >> 5) * 32;
        int tx = tid & 31, ty = tid >> 5;       // 32 x 8
        __shared__ float tile[32][33];
        #pragma unroll
        for (int r = 0; r < 32; r += 8)
            tile[ty + r][tx] = W[(size_t)(bk + ty + r) * D_DIM + bn + tx];
        __syncthreads();
        #pragma unroll
        for (int r = 0; r < 32; r += 8) {
            float v = tile[tx][ty + r];          // = W[bk+tx][bn+ty+r]
            __nv_bfloat16 hi = __float2bfloat16(v);
            float lo = v - __bfloat162float(hi);
            size_t off = (size_t)(bn + ty + r) * D_DIM + bk + tx;   // wT[n][k]
            g_whiT[off] = hi;
            g_wloT[off] = __float2bfloat16(lo);
        }
    }
}

// ---------------- common MMA machinery ----------------
#define STAGE_B 32768           // A 16KB + B 16KB
#define NSTAGE 3
#define MMA_SMEM (NSTAGE * STAGE_B)

#define CPA16(dst, src) \
    asm volatile("cp.async.cg.shared.global [%0], [%1], 16;" :: "r"(dst), "l"(src))
#define CPA_COMMIT() asm volatile("cp.async.commit_group;" ::: "memory")
#define CPA_WAIT1()  asm volatile("cp.async.wait_group 1;" ::: "memory")

#define LDMX4(r0, r1, r2, r3, addr) \
    asm volatile("ldmatrix.sync.aligned.m8n8.x4.shared.b16 {%0,%1,%2,%3}, [%4];" \
        : "=r"(r0), "=r"(r1), "=r"(r2), "=r"(r3) : "r"(addr))

#define MMA16816(d, a, b0, b1) \
    asm volatile("mma.sync.aligned.m16n8k16.row.col.f32.bf16.bf16.f32 " \
        "{%0,%1,%2,%3}, {%4,%5,%6,%7}, {%8,%9}, {%0,%1,%2,%3};" \
        : "+f"((d)[0]), "+f"((d)[1]), "+f"((d)[2]), "+f"((d)[3]) \
        : "r"((a)[0]), "r"((a)[1]), "r"((a)[2]), "r"((a)[3]), "r"(b0), "r"(b1))

#define INSERT(q, v, ix) do { \
    if ((v) > tv1[q] || ((v) == tv1[q] && (ix) < ti1[q])) { \
        tv2[q] = tv1[q]; ti2[q] = ti1[q]; tv1[q] = (v); ti1[q] = (ix); \
    } else if ((v) > tv2[q] || ((v) == tv2[q] && (ix) < ti2[q])) { \
        tv2[q] = (v); ti2[q] = (ix); \
    } } while (0)

#define LOADER_SETUP() \
    int lrow[4], lkg[4]; uint32_t ldst[4]; \
    _Pragma("unroll") \
    for (int i = 0; i < 4; i++) { \
        int u = tid + i * 256; \
        lrow[i] = u >> 3; lkg[i] = u & 7; \
        ldst[i] = (uint32_t)(lrow[i] * 128 + ((lkg[i] ^ (lrow[i] & 7)) << 4)); \
    }

#define LDM_SETUP() \
    int a_row[2], b_row[4]; int a_kgb, b_kgb; \
    { \
        a_kgb = lane >> 4; \
        a_row[0] = wm + (lane & 15); \
        a_row[1] = wm + 16 + (lane & 15); \
        int bg = lane >> 3; \
        b_kgb = bg & 1; \
        _Pragma("unroll") \
        for (int p = 0; p < 4; p++) \
            b_row[p] = wn + (p * 2 + (bg >> 1)) * 8 + (lane & 7); \
    }

#define COMPUTE_CHUNK(aS, bS) \
    _Pragma("unroll") \
    for (int ks = 0; ks < 4; ks++) { \
        uint32_t a[2][4]; \
        _Pragma("unroll") \
        for (int mt = 0; mt < 2; mt++) { \
            int kg = ks * 2 + a_kgb; \
            uint32_t addr = (aS) + a_row[mt] * 128 + ((kg ^ (a_row[mt] & 7)) << 4); \
            LDMX4(a[mt][0], a[mt][1], a[mt][2], a[mt][3], addr); \
        } \
        _Pragma("unroll") \
        for (int p = 0; p < 4; p++) { \
            uint32_t b[4]; \
            int kg = ks * 2 + b_kgb; \
            uint32_t addr = (bS) + b_row[p] * 128 + ((kg ^ (b_row[p] & 7)) << 4); \
            LDMX4(b[0], b[1], b[2], b[3], addr); \
            _Pragma("unroll") \
            for (int mt = 0; mt < 2; mt++) { \
                MMA16816(acc[mt][p * 2 + 0], a[mt], b[0], b[1]); \
                MMA16816(acc[mt][p * 2 + 1], a[mt], b[2], b[3]); \
            } \
        } \
    }

// ---------------- bf16 mma sim-GEMM + per-row top-2 (R9 config) ----------------
// grid (64 m-tiles, 64 col-groups). Each CTA: 128 rows x 256 cols (2 n-tiles),
// 32 flat K-chunks, 3-stage cp.async ring, 1 sync per chunk.
__global__ void __launch_bounds__(256, 2)
simmma_kernel() {
    extern __shared__ char sm[];
    uint32_t sb = smem_u32(sm);
    const int tid = threadIdx.x, lane = tid & 31, w = tid >> 5;
    const int wm = (w & 3) * 32, wn = (w >> 2) * 64;
    const int rb = blockIdx.x * 128;
    const int cb = blockIdx.y * 256;

    LOADER_SETUP();
    LDM_SETUP();

    float tv1[4], tv2[4]; int ti1[4], ti2[4];
    #pragma unroll
    for (int q = 0; q < 4; q++) { tv1[q] = -2.f; tv2[q] = -2.f; ti1[q] = 0; ti2[q] = 0; }

    const __nv_bfloat16* Ab = g_qbf + (size_t)rb * D_DIM;
    const __nv_bfloat16* Bb = g_kbf + (size_t)cb * D_DIM;

    // prologue: chunks 0,1 -> stages 0,1  (chunk h: nt = h>>4, kc = h&15)
    #pragma unroll
    for (int h = 0; h < 2; h++) {
        uint32_t stg = sb + h * STAGE_B;
        #pragma unroll
        for (int i = 0; i < 4; i++) {
            CPA16(stg + ldst[i],         Ab + (size_t)lrow[i] * D_DIM + h * 64 + lkg[i] * 8);
            CPA16(stg + 16384 + ldst[i], Bb + (size_t)lrow[i] * D_DIM + h * 64 + lkg[i] * 8);
        }
        CPA_COMMIT();
    }
    CPA_WAIT1();
    __syncthreads();

    float acc[2][8][4];
    int st = 0;
    #pragma unroll 1
    for (int g = 0; g < 32; g++) {
        int kc = g & 15, nt = g >> 4;
        if (kc == 0) {
            #pragma unroll
            for (int mt = 0; mt < 2; mt++)
                #pragma unroll
                for (int j = 0; j < 8; j++)
                    #pragma unroll
                    for (int c = 0; c < 4; c++) acc[mt][j][c] = 0.f;
        }
        uint32_t aS = sb + st * STAGE_B;
        uint32_t bS = aS + 16384;
        COMPUTE_CHUNK(aS, bS);
        if (kc == 15) {
            int colbase = cb + nt * 128 + wn + (lane & 3) * 2;
            #pragma unroll
            for (int mt = 0; mt < 2; mt++)
                #pragma unroll
                for (int h2 = 0; h2 < 2; h2++) {
                    int q = mt * 2 + h2;
                    #pragma unroll
                    for (int j = 0; j < 8; j++) {
                        float v0 = acc[mt][j][h2 * 2 + 0];
                        float v1 = acc[mt][j][h2 * 2 + 1];
                        int c0 = colbase + j * 8;
                        INSERT(q, v0, c0);
                        INSERT(q, v1, c0 + 1);
                    }
                }
        }
        int h = g + 2;
        if (h < 32) {
            int kch = h & 15, nth = h >> 4;
            int sti = st + 2; if (sti >= 3) sti -= 3;
            uint32_t stg = sb + sti * STAGE_B;
            const __nv_bfloat16* Ac = Ab + kch * 64;
            const __nv_bfloat16* Bc = Bb + (size_t)(nth * 128) * D_DIM + kch * 64;
            #pragma unroll
            for (int i = 0; i < 4; i++) {
                CPA16(stg + ldst[i],         Ac + (size_t)lrow[i] * D_DIM + lkg[i] * 8);
                CPA16(stg + 16384 + ldst[i], Bc + (size_t)lrow[i] * D_DIM + lkg[i] * 8);
            }
        }
        CPA_COMMIT();
        CPA_WAIT1();
        __syncthreads();
        st++; if (st >= 3) st = 0;
    }

    // merge top-2 across the 4 lanes of each quad
    #pragma unroll
    for (int off = 1; off <= 2; off <<= 1) {
        #pragma unroll
        for (int q = 0; q < 4; q++) {
            float ov1 = __shfl_xor_sync(0xffffffffu, tv1[q], off);
            int   oi1 = __shfl_xor_sync(0xffffffffu, ti1[q], off);
            float ov2 = __shfl_xor_sync(0xffffffffu, tv2[q], off);
            int   oi2 = __shfl_xor_sync(0xffffffffu, ti2[q], off);
            INSERT(q, ov1, oi1);
            INSERT(q, ov2, oi2);
        }
    }
    if ((lane & 3) == 0) {
        int slot = blockIdx.y * 2 + (w >> 2);
        #pragma unroll
        for (int q = 0; q < 4; q++) {
            int row = rb + wm + (q >> 1) * 16 + (q & 1) * 8 + (lane >> 2);
            g_cv[row][slot][0] = tv1[q]; g_ci[row][slot][0] = ti1[q];
            g_cv[row][slot][1] = tv2[q]; g_ci[row][slot][1] = ti2[q];
        }
    }
}

// ---------------- fused: exact fp32 rescore + STE + LayerNorm ----------------
__global__ void rescore_ln_kernel(const float* __restrict__ X, const float* __restrict__ Dw,
                                  const float* __restrict__ gamma, const float* __restrict__ beta,
                                  float* __restrict__ out, int write_aux) {
    int row = blockIdx.x;
    int tid = threadIdx.x;
    __shared__ float red[32];
    __shared__ int cl[32];
    __shared__ int s_cnt;
    __shared__ float s_best; __shared__ int s_bidx;
    float mv = g_cv[row][tid >> 1][tid & 1];
    int   mi = g_ci[row][tid >> 1][tid & 1];
    float vmax = block_max_256(mv, red);
    if (tid == 0) { s_cnt = 0; s_best = -9.f; s_bidx = 0x7FFFFFFF; }
    __syncthreads();
    if (mv >= vmax - 1e-3f) {
        int pos = atomicAdd(&s_cnt, 1);
        if (pos < 32) cl[pos] = mi;
    }
    __syncthreads();
    int cnt = s_cnt; if (cnt > 32) cnt = 32;
    float inva = g_inv_x[row];
    const float4* xr = (const float4*)(X + (size_t)row * D_DIM);
    float4 xv = xr[tid];
    for (int c = 0; c < cnt; c++) {
        int idx = cl[c];
        const float4* dr = (const float4*)(Dw + (size_t)idx * D_DIM);
        float4 dv = dr[tid];
        float part = xv.x * dv.x + xv.y * dv.y + xv.z * dv.z + xv.w * dv.w;
        float tot = block_sum_256(part, red);
        if (tid == 0) {
            float sim = tot * inva * g_inv_d[idx];
            if (sim > s_best || (sim == s_best && idx < s_bidx)) { s_best = sim; s_bidx = idx; }
        }
        __syncthreads();
    }
    if (tid == 0 && write_aux) { out[row] = (float)s_bidx; out[R_TOT + row] = s_best; }
    __syncthreads();
    int idx = s_bidx;

    // ---- STE + LayerNorm ----
    const float* xrf = X + (size_t)row * D_DIM;
    const float* zr = Dw + (size_t)idx * D_DIM;
    float ev[4];
    float s = 0.f;
    #pragma unroll
    for (int t = 0; t < 4; t++) {
        int j = t * 256 + tid;
        float xvv = xrf[j], zv = zr[j];
        ev[t] = (zv - xvv) + xvv;
        s += ev[t];
    }
    float mu = block_sum_256(s, red) * (1.0f / D_DIM);
    float ss = 0.f;
    #pragma unroll
    for (int t = 0; t < 4; t++) { float d = ev[t] - mu; ss += d * d; }
    float var = block_sum_256(ss, red) * (1.0f / D_DIM);
    float rsig = rsqrtf(var + 1e-6f);
    #pragma unroll
    for (int t = 0; t < 4; t++) {
        int j = t * 256 + tid;
        float v = (ev[t] - mu) * rsig * gamma[j] + beta[j];
        __nv_bfloat16 hi = __float2bfloat16(v);
        float lo = v - __bfloat162float(hi);
        size_t off = (size_t)row * D_DIM + j;
        g_ehi[off] = hi;
        g_elo[off] = __float2bfloat16(lo);
    }
}

// ---------------- output projection: 3-term bf16 split GEMM ----------------
__global__ void __launch_bounds__(256, 2)
outmma_kernel(float* __restrict__ Out) {
    extern __shared__ char sm[];
    uint32_t sb = smem_u32(sm);
    const int tid = threadIdx.x, lane = tid & 31, w = tid >> 5;
    const int wm = (w & 3) * 32, wn = (w >> 2) * 64;
    const int rb = blockIdx.x * 128;
    const int cbN = blockIdx.y * 128;

    LOADER_SETUP();
    LDM_SETUP();

    const int NCH = 48;

    auto a_src = [&](int h) -> const __nv_bfloat16* {
        int seg = h >> 4, kc = h & 15;
        const __nv_bfloat16* base = (seg < 2) ? g_ehi : g_elo;
        return base + (size_t)rb * D_DIM + kc * 64;
    };
    auto b_src = [&](int h) -> const __nv_bfloat16* {
        int seg = h >> 4, kc = h & 15;
        const __nv_bfloat16* base = (seg == 1) ? g_wloT : g_whiT;
        return base + (size_t)cbN * D_DIM + kc * 64;
    };

    #pragma unroll
    for (int h = 0; h < 2; h++) {
        uint32_t stg = sb + h * STAGE_B;
        const __nv_bfloat16* Ac = a_src(h);
        const __nv_bfloat16* Bc = b_src(h);
        #pragma unroll
        for (int i = 0; i < 4; i++) {
            CPA16(stg + ldst[i],         Ac + (size_t)lrow[i] * D_DIM + lkg[i] * 8);
            CPA16(stg + 16384 + ldst[i], Bc + (size_t)lrow[i] * D_DIM + lkg[i] * 8);
        }
        CPA_COMMIT();
    }
    CPA_WAIT1();
    __syncthreads();

    float acc[2][8][4];
    #pragma unroll
    for (int mt = 0; mt < 2; mt++)
        #pragma unroll
        for (int j = 0; j < 8; j++)
            #pragma unroll
            for (int c = 0; c < 4; c++) acc[mt][j][c] = 0.f;

    int st = 0;
    #pragma unroll 1
    for (int g = 0; g < NCH; g++) {
        uint32_t aS = sb + st * STAGE_B;
        uint32_t bS = aS + 16384;
        COMPUTE_CHUNK(aS, bS);
        int h = g + 2;
        if (h < NCH) {
            int sti = st + 2; if (sti >= 3) sti -= 3;
            uint32_t stg = sb + sti * STAGE_B;
            const __nv_bfloat16* Ac = a_src(h);
            const __nv_bfloat16* Bc = b_src(h);
            #pragma unroll
            for (int i = 0; i < 4; i++) {
                CPA16(stg + ldst[i],         Ac + (size_t)lrow[i] * D_DIM + lkg[i] * 8);
                CPA16(stg + 16384 + ldst[i], Bc + (size_t)lrow[i] * D_DIM + lkg[i] * 8);
            }
        }
        CPA_COMMIT();
        CPA_WAIT1();
        __syncthreads();
        st++; if (st >= 3) st = 0;
    }

    #pragma unroll
    for (int mt = 0; mt < 2; mt++) {
        int row0 = rb + wm + mt * 16 + (lane >> 2);
        #pragma unroll
        for (int j = 0; j < 8; j++) {
            int col = cbN + wn + j * 8 + (lane & 3) * 2;
            *(float2*)(Out + (size_t)row0 * D_DIM + col) = make_float2(acc[mt][j][0], acc[mt][j][1]);
            *(float2*)(Out + (size_t)(row0 + 8) * D_DIM + col) = make_float2(acc[mt][j][2], acc[mt][j][3]);
        }
    }
}

extern "C" void kernel_launch(void* const* d_in, const int* in_sizes, int n_in,
                              void* d_out, int out_size) {
    const float* x     = (const float*)d_in[0];
    const float* dw    = (const float*)d_in[1];
    const float* gamma = (const float*)d_in[2];
    const float* beta  = (const float*)d_in[3];
    const float* ow    = (const float*)d_in[4];
    float* out = (float*)d_out;

    const int out_elems = R_TOT * D_DIM;
    int write_aux = (out_size >= out_elems + 2 * R_TOT) ? 1 : 0;
    size_t out_off = write_aux ? (size_t)(2 * R_TOT) : 0;

    cudaFuncSetAttribute(simmma_kernel, cudaFuncAttributeMaxDynamicSharedMemorySize, MMA_SMEM);
    cudaFuncSetAttribute(outmma_kernel, cudaFuncAttributeMaxDynamicSharedMemorySize, MMA_SMEM);

    preproc_kernel<<<R_TOT + V_DIM + 1024, 256>>>(x, dw, ow);
    simmma_kernel<<<dim3(R_TOT / 128, NGRP), 256, MMA_SMEM>>>();
    rescore_ln_kernel<<<R_TOT, 256>>>(x, dw, gamma, beta, out, write_aux);
    outmma_kernel<<<dim3(R_TOT / 128, D_DIM / 128), 256, MMA_SMEM>>>(out + out_off);
}